// round 14
// baseline (speedup 1.0000x reference)
#include <cuda_runtime.h>
#include <cuda_bf16.h>
#include <cuda_pipeline.h>
#include <math.h>

#define HID   4096
#define NH    32
#define NKV   8
#define HD    128
#define B_    4
#define S_    1024
#define M_TOT (B_ * S_)
#define QKV_N (NH * HD + 2 * NKV * HD)
#define K_OFF (NH * HD)
#define V_OFF (NH * HD + NKV * HD)

// ---------------- scratch (device globals: allocation-guard safe) ------------
__device__ float g_qkv[(size_t)M_TOT * QKV_N];
__device__ float g_q[(size_t)B_ * NH * S_ * HD];
__device__ float g_k[(size_t)B_ * NKV * S_ * HD];
__device__ float g_v[(size_t)B_ * NKV * S_ * HD];
__device__ __nv_bfloat16 g_ah[(size_t)M_TOT * HID];
__device__ __nv_bfloat16 g_al[(size_t)M_TOT * HID];
__device__ __nv_bfloat16 g_bh[(size_t)QKV_N * HID];
__device__ __nv_bfloat16 g_bl[(size_t)QKV_N * HID];

// ---------------- fp32 -> bf16 hi/lo split -----------------------------------
__global__ __launch_bounds__(256) void split_fp32(
    const float* __restrict__ x, __nv_bfloat16* __restrict__ hi,
    __nv_bfloat16* __restrict__ lo, int n)
{
    int i = (blockIdx.x * 256 + threadIdx.x) * 4;
    if (i >= n) return;
    float4 v = *(const float4*)(x + i);
    float v0 = v.x, v1 = v.y, v2 = v.z, v3 = v.w;
    __nv_bfloat16 h0 = __float2bfloat16_rn(v0);
    __nv_bfloat16 h1 = __float2bfloat16_rn(v1);
    __nv_bfloat16 h2 = __float2bfloat16_rn(v2);
    __nv_bfloat16 h3 = __float2bfloat16_rn(v3);
    __nv_bfloat16 l0 = __float2bfloat16_rn(v0 - __bfloat162float(h0));
    __nv_bfloat16 l1 = __float2bfloat16_rn(v1 - __bfloat162float(h1));
    __nv_bfloat16 l2 = __float2bfloat16_rn(v2 - __bfloat162float(h2));
    __nv_bfloat16 l3 = __float2bfloat16_rn(v3 - __bfloat162float(h3));
    *(__nv_bfloat162*)(hi + i)     = __halves2bfloat162(h0, h1);
    *(__nv_bfloat162*)(hi + i + 2) = __halves2bfloat162(h2, h3);
    *(__nv_bfloat162*)(lo + i)     = __halves2bfloat162(l0, l1);
    *(__nv_bfloat162*)(lo + i + 2) = __halves2bfloat162(l2, l3);
}

// ---------------- mma.sync helpers (single-line asm) -------------------------
__device__ __forceinline__ unsigned smem_u32(const void* p) {
    return (unsigned)__cvta_generic_to_shared(p);
}
__device__ __forceinline__ void ldsm4(unsigned& r0, unsigned& r1, unsigned& r2, unsigned& r3, unsigned a) {
    asm volatile("ldmatrix.sync.aligned.m8n8.x4.shared.b16 {%0,%1,%2,%3},[%4];" : "=r"(r0), "=r"(r1), "=r"(r2), "=r"(r3) : "r"(a));
}
__device__ __forceinline__ void mma16816(float* d, const unsigned* a, const unsigned* b) {
    asm volatile("mma.sync.aligned.m16n8k16.row.col.f32.bf16.bf16.f32 {%0,%1,%2,%3},{%4,%5,%6,%7},{%8,%9},{%0,%1,%2,%3};" : "+f"(d[0]), "+f"(d[1]), "+f"(d[2]), "+f"(d[3]) : "r"(a[0]), "r"(a[1]), "r"(a[2]), "r"(a[3]), "r"(b[0]), "r"(b[1]));
}

// ---------------- tensor GEMM: C[m][n] = sum_k A[m][k]*B[n][k] ---------------
// 256x128x32 CTA tile, 512 threads (16 warps, 4/SMSP), bf16x3, 3-stage pipe.
// Stage layout (bytes): [Ah 20480][Al 20480][Bh 10240][Bl 10240] = 61440.
#define SSTE  40
#define STGB  61440
#define GSMEM (3 * STGB)

__device__ __forceinline__ void gfill(
    char* sb, const __nv_bfloat16* Ah, const __nv_bfloat16* Al,
    const __nv_bfloat16* Bh, const __nv_bfloat16* Bl,
    int m0, int n0, int kc, int K, int t)
{
#pragma unroll
    for (int i = 0; i < 6; i++) {
        int v = t + i * 512;
        if (v < 1024) {
            int row = v >> 2, ku = v & 3;
            __pipeline_memcpy_async(sb + row * 80 + ku * 16,
                                    Ah + (size_t)(m0 + row) * K + kc + ku * 8, 16);
        } else if (v < 2048) {
            int u = v - 1024;
            int row = u >> 2, ku = u & 3;
            __pipeline_memcpy_async(sb + 20480 + row * 80 + ku * 16,
                                    Al + (size_t)(m0 + row) * K + kc + ku * 8, 16);
        } else if (v < 2560) {
            int u = v - 2048;
            int row = u >> 2, ku = u & 3;
            __pipeline_memcpy_async(sb + 40960 + row * 80 + ku * 16,
                                    Bh + (size_t)(n0 + row) * K + kc + ku * 8, 16);
        } else {
            int u = v - 2560;
            int row = u >> 2, ku = u & 3;
            __pipeline_memcpy_async(sb + 51200 + row * 80 + ku * 16,
                                    Bl + (size_t)(n0 + row) * K + kc + ku * 8, 16);
        }
    }
    __pipeline_commit();
}

__global__ __launch_bounds__(512, 1) void gemm_mma(
    const __nv_bfloat16* __restrict__ Ah, const __nv_bfloat16* __restrict__ Al,
    const __nv_bfloat16* __restrict__ Bh, const __nv_bfloat16* __restrict__ Bl,
    float* __restrict__ C, int M, int N, int K)
{
    extern __shared__ char smg[];
    const int t = threadIdx.x;
    const int l = t & 31, w = t >> 5;
    const int m0 = blockIdx.y * 256, n0 = blockIdx.x * 128;
    const int wm = (w & 3) * 64, wn = (w >> 2) * 32;

    float acc[4][4][4];
#pragma unroll
    for (int i = 0; i < 4; i++)
#pragma unroll
        for (int j = 0; j < 4; j++)
#pragma unroll
            for (int r = 0; r < 4; r++) acc[i][j][r] = 0.f;

    const int nc = K >> 5;

    gfill(smg,            Ah, Al, Bh, Bl, m0, n0, 0,  K, t);
    gfill(smg + STGB,     Ah, Al, Bh, Bl, m0, n0, 32, K, t);
    gfill(smg + 2 * STGB, Ah, Al, Bh, Bl, m0, n0, 64, K, t);

    // per-lane ldmatrix byte offsets within a stage
    const int aoff = ((wm + (l & 15)) * SSTE + (l >> 4) * 8) * 2;
    const int boff = 40960 + ((wn + (l & 7) + ((l >> 4) << 3)) * SSTE + ((l >> 3) & 1) * 8) * 2;

    for (int c = 0; c < nc; c++) {
        if (c <= nc - 3)      __pipeline_wait_prior(2);
        else if (c == nc - 2) __pipeline_wait_prior(1);
        else                  __pipeline_wait_prior(0);
        __syncthreads();

        unsigned sb = smem_u32(smg) + (unsigned)((c % 3) * STGB);

#pragma unroll
        for (int ks = 0; ks < 2; ks++) {
            unsigned ah[4][4], al[4][4], bh[4][2], bl[4][2];
#pragma unroll
            for (int i = 0; i < 4; i++) {
                unsigned ao = sb + aoff + (i * 16 * SSTE + ks * 16) * 2;
                ldsm4(ah[i][0], ah[i][1], ah[i][2], ah[i][3], ao);
                ldsm4(al[i][0], al[i][1], al[i][2], al[i][3], ao + 20480);
            }
#pragma unroll
            for (int j = 0; j < 2; j++) {
                unsigned bo = sb + boff + (j * 16 * SSTE + ks * 16) * 2;
                unsigned r0, r1, r2, r3;
                ldsm4(r0, r1, r2, r3, bo);
                bh[2*j][0] = r0; bh[2*j][1] = r1; bh[2*j+1][0] = r2; bh[2*j+1][1] = r3;
                ldsm4(r0, r1, r2, r3, bo + 10240);
                bl[2*j][0] = r0; bl[2*j][1] = r1; bl[2*j+1][0] = r2; bl[2*j+1][1] = r3;
            }
#pragma unroll
            for (int i = 0; i < 4; i++)
#pragma unroll
                for (int j = 0; j < 4; j++) mma16816(acc[i][j], ah[i], bh[j]);
#pragma unroll
            for (int i = 0; i < 4; i++)
#pragma unroll
                for (int j = 0; j < 4; j++) mma16816(acc[i][j], ah[i], bl[j]);
#pragma unroll
            for (int i = 0; i < 4; i++)
#pragma unroll
                for (int j = 0; j < 4; j++) mma16816(acc[i][j], al[i], bh[j]);
        }
        __syncthreads();

        if (c + 3 < nc)
            gfill(smg + (c % 3) * STGB, Ah, Al, Bh, Bl, m0, n0, (c + 3) << 5, K, t);
    }

#pragma unroll
    for (int i = 0; i < 4; i++) {
        int m = m0 + wm + i * 16 + (l >> 2);
#pragma unroll
        for (int j = 0; j < 4; j++) {
            int n = n0 + wn + j * 8 + (l & 3) * 2;
            *(float2*)&C[(size_t)m * N + n]       = make_float2(acc[i][j][0], acc[i][j][1]);
            *(float2*)&C[(size_t)(m + 8) * N + n] = make_float2(acc[i][j][2], acc[i][j][3]);
        }
    }
}

// ---------------- fused RMSNorm + RoPE + scatter -----------------------------
__global__ __launch_bounds__(128) void normrope(
    const float* __restrict__ qkv, const int* __restrict__ positions,
    const float* __restrict__ qw, const float* __restrict__ kw)
{
    const int hh = blockIdx.x;
    const int m  = blockIdx.y;
    const int d  = threadIdx.x;
    const int b  = m >> 10, s = m & 1023;

    if (hh >= NH + NKV) {
        int vh = hh - (NH + NKV);
        g_v[((size_t)(b * NKV + vh) * S_ + s) * HD + d] =
            qkv[(size_t)m * QKV_N + V_OFF + vh * HD + d];
        return;
    }
    const bool isq = (hh < NH);
    const int off = isq ? hh * HD : K_OFF + (hh - NH) * HD;
    float x = qkv[(size_t)m * QKV_N + off + d];

    float ss = x * x;
#pragma unroll
    for (int o = 16; o; o >>= 1) ss += __shfl_xor_sync(0xffffffffu, ss, o);
    __shared__ float wsum[4];
    __shared__ float sh[128];
    if ((d & 31) == 0) wsum[d >> 5] = ss;
    __syncthreads();
    float tot = wsum[0] + wsum[1] + wsum[2] + wsum[3];
    float r = rsqrtf(tot * (1.f / HD) + 1e-6f);
    float xn = x * r * (isq ? qw[d] : kw[d]);
    sh[d] = xn;
    __syncthreads();

    int pos = positions[s];
    int i = d & 63;
    float inv = exp2f(-(float)i * (13.287712379549449f / 64.f));
    float ang = (float)pos * inv;
    float sn, cs;
    sincosf(ang, &sn, &cs);
    float out = (d < 64) ? (xn * cs - sh[d + 64] * sn)
                         : (xn * cs + sh[d - 64] * sn);
    if (isq) g_q[((size_t)(b * NH + hh) * S_ + s) * HD + d] = out;
    else     g_k[((size_t)(b * NKV + (hh - NH)) * S_ + s) * HD + d] = out;
}

// ---------------- flash attention (causal, GQA) ------------------------------
// epilogue writes bf16 hi/lo directly into g_ah/g_al (A of the O-projection).
#define SS_STRIDE 65
#define ATT_SMEM_FLOATS (8192 + 8192 + 8192 + 64 * SS_STRIDE)
#define ATT_SMEM_BYTES  (ATT_SMEM_FLOATS * 4)

__global__ __launch_bounds__(256) void attn_kernel()
{
    extern __shared__ float smf[];
    float* QsT = smf;
    float* KsT = smf + 8192;
    float* Vs  = smf + 16384;
    float* Ss  = smf + 24576;

    const int t  = threadIdx.x;
    const int qt = blockIdx.x, h = blockIdx.y, b = blockIdx.z;
    const int kh = h >> 2;
    const float* qbase = g_q + ((size_t)(b * NH + h) * S_ + qt * 64) * HD;
    const float* kbase = g_k + (size_t)(b * NKV + kh) * S_ * HD;
    const float* vbase = g_v + (size_t)(b * NKV + kh) * S_ * HD;

#pragma unroll
    for (int it = 0; it < 8; it++) {
        int idx = t + it * 256;
        int dq = idx & 31, r = idx >> 5;
        float4 v4 = *(const float4*)(qbase + r * HD + dq * 4);
        int cc = r ^ ((dq & 7) << 2);
        QsT[(dq * 4 + 0) * 64 + cc] = v4.x;
        QsT[(dq * 4 + 1) * 64 + cc] = v4.y;
        QsT[(dq * 4 + 2) * 64 + cc] = v4.z;
        QsT[(dq * 4 + 3) * 64 + cc] = v4.w;
    }

    const int tx = t & 15, ty = t >> 4;
    const int rp = t & 31, wch = t >> 5;
    const int d0 = wch * 16;
    const int r0 = rp * 2;
    const int sq0 = qt * 64;

    float m0v = -3.0e38f, m1v = -3.0e38f, l0 = 0.f, l1 = 0.f;
    float o0[16], o1[16];
#pragma unroll
    for (int i = 0; i < 16; i++) { o0[i] = 0.f; o1[i] = 0.f; }

    for (int kt = 0; kt <= qt; kt++) {
        __syncthreads();
        const float* kb = kbase + (size_t)kt * 64 * HD;
        const float* vb = vbase + (size_t)kt * 64 * HD;
#pragma unroll
        for (int it = 0; it < 8; it++) {
            int idx = t + it * 256;
            int dq = idx & 31, r = idx >> 5;
            float4 k4 = *(const float4*)(kb + r * HD + dq * 4);
            int cc = r ^ ((dq & 7) << 2);
            KsT[(dq * 4 + 0) * 64 + cc] = k4.x;
            KsT[(dq * 4 + 1) * 64 + cc] = k4.y;
            KsT[(dq * 4 + 2) * 64 + cc] = k4.z;
            KsT[(dq * 4 + 3) * 64 + cc] = k4.w;
            float4 v4 = *(const float4*)(vb + r * HD + dq * 4);
            *(float4*)&Vs[r * HD + dq * 4] = v4;
        }
        __syncthreads();

        float sc[4][4];
#pragma unroll
        for (int i = 0; i < 4; i++)
#pragma unroll
            for (int j = 0; j < 4; j++) sc[i][j] = 0.f;

        for (int dq = 0; dq < 32; dq++) {
            int sw = (dq & 7) << 2;
#pragma unroll
            for (int ii = 0; ii < 4; ii++) {
                int d = dq * 4 + ii;
                float4 a = *(const float4*)&QsT[d * 64 + ((ty * 4) ^ sw)];
                float4 bq = *(const float4*)&KsT[d * 64 + ((tx * 4) ^ sw)];
                float a0 = a.x, a1 = a.y, a2 = a.z, a3 = a.w;
                float b0 = bq.x, b1 = bq.y, b2 = bq.z, b3 = bq.w;
                sc[0][0] = fmaf(a0, b0, sc[0][0]); sc[0][1] = fmaf(a0, b1, sc[0][1]);
                sc[0][2] = fmaf(a0, b2, sc[0][2]); sc[0][3] = fmaf(a0, b3, sc[0][3]);
                sc[1][0] = fmaf(a1, b0, sc[1][0]); sc[1][1] = fmaf(a1, b1, sc[1][1]);
                sc[1][2] = fmaf(a1, b2, sc[1][2]); sc[1][3] = fmaf(a1, b3, sc[1][3]);
                sc[2][0] = fmaf(a2, b0, sc[2][0]); sc[2][1] = fmaf(a2, b1, sc[2][1]);
                sc[2][2] = fmaf(a2, b2, sc[2][2]); sc[2][3] = fmaf(a2, b3, sc[2][3]);
                sc[3][0] = fmaf(a3, b0, sc[3][0]); sc[3][1] = fmaf(a3, b1, sc[3][1]);
                sc[3][2] = fmaf(a3, b2, sc[3][2]); sc[3][3] = fmaf(a3, b3, sc[3][3]);
            }
        }
        const float scl = 0.08838834764831845f;
        const bool diag = (kt == qt);
#pragma unroll
        for (int i = 0; i < 4; i++) {
            int sq = sq0 + ty * 4 + i;
#pragma unroll
            for (int j = 0; j < 4; j++) {
                int sk = kt * 64 + tx * 4 + j;
                float val = sc[i][j] * scl;
                if (diag && sk > sq) val = -3.0e38f;
                Ss[(ty * 4 + i) * SS_STRIDE + tx * 4 + j] = val;
            }
        }
        __syncthreads();

        float tm0 = -3.0e38f, tm1 = -3.0e38f;
        for (int c = 0; c < 64; c++) {
            tm0 = fmaxf(tm0, Ss[r0 * SS_STRIDE + c]);
            tm1 = fmaxf(tm1, Ss[(r0 + 1) * SS_STRIDE + c]);
        }
        float nm0 = fmaxf(m0v, tm0), nm1 = fmaxf(m1v, tm1);
        float al0 = __expf(m0v - nm0), al1 = __expf(m1v - nm1);
        l0 *= al0; l1 *= al1;
#pragma unroll
        for (int i = 0; i < 16; i++) { o0[i] *= al0; o1[i] *= al1; }

        for (int c = 0; c < 64; c++) {
            float p0 = __expf(Ss[r0 * SS_STRIDE + c] - nm0);
            float p1 = __expf(Ss[(r0 + 1) * SS_STRIDE + c] - nm1);
            l0 += p0; l1 += p1;
            const float4* vp = (const float4*)&Vs[c * HD + d0];
#pragma unroll
            for (int q4 = 0; q4 < 4; q4++) {
                float4 vv = vp[q4];
                o0[q4*4+0] += p0 * vv.x; o0[q4*4+1] += p0 * vv.y;
                o0[q4*4+2] += p0 * vv.z; o0[q4*4+3] += p0 * vv.w;
                o1[q4*4+0] += p1 * vv.x; o1[q4*4+1] += p1 * vv.y;
                o1[q4*4+2] += p1 * vv.z; o1[q4*4+3] += p1 * vv.w;
            }
        }
        m0v = nm0; m1v = nm1;
    }

    // epilogue: normalize + bf16 hi/lo split directly into O-GEMM A buffers
    float inv0 = 1.f / l0, inv1 = 1.f / l1;
    size_t mrow = (size_t)(b * S_ + sq0 + r0);
    size_t base0 = mrow * HID + h * HD + d0;
    size_t base1 = base0 + HID;
#pragma unroll
    for (int q4 = 0; q4 < 4; q4++) {
#pragma unroll
        for (int e = 0; e < 4; e += 2) {
            float va = o0[q4*4+e]   * inv0;
            float vb = o0[q4*4+e+1] * inv0;
            __nv_bfloat16 ha = __float2bfloat16_rn(va);
            __nv_bfloat16 hb = __float2bfloat16_rn(vb);
            __nv_bfloat16 la = __float2bfloat16_rn(va - __bfloat162float(ha));
            __nv_bfloat16 lb = __float2bfloat16_rn(vb - __bfloat162float(hb));
            *(__nv_bfloat162*)(g_ah + base0 + q4*4 + e) = __halves2bfloat162(ha, hb);
            *(__nv_bfloat162*)(g_al + base0 + q4*4 + e) = __halves2bfloat162(la, lb);
            float vc = o1[q4*4+e]   * inv1;
            float vd = o1[q4*4+e+1] * inv1;
            __nv_bfloat16 hc = __float2bfloat16_rn(vc);
            __nv_bfloat16 hd = __float2bfloat16_rn(vd);
            __nv_bfloat16 lc = __float2bfloat16_rn(vc - __bfloat162float(hc));
            __nv_bfloat16 ld = __float2bfloat16_rn(vd - __bfloat162float(hd));
            *(__nv_bfloat162*)(g_ah + base1 + q4*4 + e) = __halves2bfloat162(hc, hd);
            *(__nv_bfloat162*)(g_al + base1 + q4*4 + e) = __halves2bfloat162(lc, ld);
        }
    }
}

// ---------------- launcher ---------------------------------------------------
extern "C" void kernel_launch(void* const* d_in, const int* in_sizes, int n_in,
                              void* d_out, int out_size)
{
    const float* h_shard   = (const float*)d_in[0];
    const int*   positions = (const int*)d_in[1];
    const float* w_qkv     = (const float*)d_in[2];
    const float* w_o       = (const float*)d_in[3];
    const float* qw        = (const float*)d_in[4];
    const float* kw        = (const float*)d_in[5];
    float* out = (float*)d_out;

    float* qkv_p = 0;
    __nv_bfloat16* ah = 0;
    __nv_bfloat16* al = 0;
    __nv_bfloat16* bh = 0;
    __nv_bfloat16* bl = 0;
    cudaGetSymbolAddress((void**)&qkv_p, g_qkv);
    cudaGetSymbolAddress((void**)&ah, g_ah);
    cudaGetSymbolAddress((void**)&al, g_al);
    cudaGetSymbolAddress((void**)&bh, g_bh);
    cudaGetSymbolAddress((void**)&bl, g_bl);

    cudaFuncSetAttribute(gemm_mma,
                         cudaFuncAttributeMaxDynamicSharedMemorySize, GSMEM);
    cudaFuncSetAttribute(attn_kernel,
                         cudaFuncAttributeMaxDynamicSharedMemorySize, ATT_SMEM_BYTES);

    const int nA  = M_TOT * HID;
    const int nBq = QKV_N * HID;
    const int nBo = HID * HID;

    split_fp32<<<nA  / 1024, 256>>>(h_shard, ah, al, nA);
    split_fp32<<<nBq / 1024, 256>>>(w_qkv,   bh, bl, nBq);

    gemm_mma<<<dim3(QKV_N / 128, M_TOT / 256), 512, GSMEM>>>(
        ah, al, bh, bl, qkv_p, M_TOT, QKV_N, HID);

    normrope<<<dim3(NH + 2 * NKV, M_TOT), 128>>>(qkv_p, positions, qw, kw);

    split_fp32<<<nBo / 1024, 256>>>(w_o, bh, bl, nBo);

    attn_kernel<<<dim3(S_ / 64, NH, B_), 256, ATT_SMEM_BYTES>>>();

    gemm_mma<<<dim3(HID / 128, M_TOT / 256), 512, GSMEM>>>(
        ah, al, bh, bl, out, M_TOT, HID, HID);
}

// round 15
// speedup vs baseline: 2.1130x; 2.1130x over previous
#include <cuda_runtime.h>
#include <cuda_fp16.h>
#include <cuda_bf16.h>
#include <cuda_pipeline.h>
#include <math.h>

#define HID   4096
#define NH    32
#define NKV   8
#define HD    128
#define B_    4
#define S_    1024
#define M_TOT (B_ * S_)
#define QKV_N (NH * HD + 2 * NKV * HD)
#define K_OFF (NH * HD)
#define V_OFF (NH * HD + NKV * HD)

// ---------------- scratch (device globals: allocation-guard safe) ------------
__device__ float g_qkv[(size_t)M_TOT * QKV_N];
__device__ float g_q[(size_t)B_ * NH * S_ * HD];
__device__ float g_k[(size_t)B_ * NKV * S_ * HD];
__device__ float g_v[(size_t)B_ * NKV * S_ * HD];
__device__ __half g_ah[(size_t)M_TOT * HID];
__device__ __half g_al[(size_t)M_TOT * HID];
__device__ __half g_bh[(size_t)QKV_N * HID];

// ---------------- fp32 -> fp16 hi/lo split -----------------------------------
__global__ __launch_bounds__(256) void split_fp16(
    const float* __restrict__ x, __half* __restrict__ hi,
    __half* __restrict__ lo, int n)
{
    int i = (blockIdx.x * 256 + threadIdx.x) * 4;
    if (i >= n) return;
    float4 v = *(const float4*)(x + i);
    float v0 = v.x, v1 = v.y, v2 = v.z, v3 = v.w;
    __half h0 = __float2half_rn(v0);
    __half h1 = __float2half_rn(v1);
    __half h2 = __float2half_rn(v2);
    __half h3 = __float2half_rn(v3);
    __half l0 = __float2half_rn(v0 - __half2float(h0));
    __half l1 = __float2half_rn(v1 - __half2float(h1));
    __half l2 = __float2half_rn(v2 - __half2float(h2));
    __half l3 = __float2half_rn(v3 - __half2float(h3));
    *(__half2*)(hi + i)     = __halves2half2(h0, h1);
    *(__half2*)(hi + i + 2) = __halves2half2(h2, h3);
    *(__half2*)(lo + i)     = __halves2half2(l0, l1);
    *(__half2*)(lo + i + 2) = __halves2half2(l2, l3);
}

// ---------------- fp32 -> fp16 (single) --------------------------------------
__global__ __launch_bounds__(256) void cvt_fp16(
    const float* __restrict__ x, __half* __restrict__ h, int n)
{
    int i = (blockIdx.x * 256 + threadIdx.x) * 4;
    if (i >= n) return;
    float4 v = *(const float4*)(x + i);
    *(__half2*)(h + i)     = __halves2half2(__float2half_rn(v.x), __float2half_rn(v.y));
    *(__half2*)(h + i + 2) = __halves2half2(__float2half_rn(v.z), __float2half_rn(v.w));
}

// ---------------- mma.sync helpers (single-line asm) -------------------------
__device__ __forceinline__ unsigned smem_u32(const void* p) {
    return (unsigned)__cvta_generic_to_shared(p);
}
__device__ __forceinline__ void ldsm4(unsigned& r0, unsigned& r1, unsigned& r2, unsigned& r3, unsigned a) {
    asm volatile("ldmatrix.sync.aligned.m8n8.x4.shared.b16 {%0,%1,%2,%3},[%4];" : "=r"(r0), "=r"(r1), "=r"(r2), "=r"(r3) : "r"(a));
}
__device__ __forceinline__ void mma16816(float* d, const unsigned* a, const unsigned* b) {
    asm volatile("mma.sync.aligned.m16n8k16.row.col.f32.f16.f16.f32 {%0,%1,%2,%3},{%4,%5,%6,%7},{%8,%9},{%0,%1,%2,%3};" : "+f"(d[0]), "+f"(d[1]), "+f"(d[2]), "+f"(d[3]) : "r"(a[0]), "r"(a[1]), "r"(a[2]), "r"(a[3]), "r"(b[0]), "r"(b[1]));
}

// ---------------- tensor GEMM: C[m][n] = sum_k A[m][k]*B[n][k] ---------------
// 128x128x32 CTA tile, 256 threads, fp16x2 (AhBh + AlBh), 3-stage pipe.
// Stage layout (bytes): [Ah 10240][Al 10240][Bh 10240] = 30720.
#define SSTE  40
#define MATB  (128 * SSTE * 2)     // 10240 B per matrix tile
#define STGB  (3 * MATB)           // 30720 B per stage
#define GSMEM (3 * STGB)           // 92160 B

__device__ __forceinline__ void gfill(
    char* sb, const __half* Ah, const __half* Al, const __half* Bh,
    int m0, int n0, int kc, int K, int t)
{
#pragma unroll
    for (int i = 0; i < 2; i++) {
        int v = t + i * 256;
        int row = v >> 2, ku = v & 3;
        int so = row * SSTE * 2 + ku * 16;
        size_t ga = (size_t)(m0 + row) * K + kc + ku * 8;
        size_t gb = (size_t)(n0 + row) * K + kc + ku * 8;
        __pipeline_memcpy_async(sb + so,            Ah + ga, 16);
        __pipeline_memcpy_async(sb + MATB + so,     Al + ga, 16);
        __pipeline_memcpy_async(sb + 2 * MATB + so, Bh + gb, 16);
    }
    __pipeline_commit();
}

__global__ __launch_bounds__(256) void gemm_mma(
    const __half* __restrict__ Ah, const __half* __restrict__ Al,
    const __half* __restrict__ Bh,
    float* __restrict__ C, int M, int N, int K)
{
    extern __shared__ char smg[];
    const int t = threadIdx.x;
    const int l = t & 31, w = t >> 5;
    const int m0 = blockIdx.y * 128, n0 = blockIdx.x * 128;
    const int wm = (w & 1) * 64, wn = (w >> 1) * 32;

    float acc[4][4][4];
#pragma unroll
    for (int i = 0; i < 4; i++)
#pragma unroll
        for (int j = 0; j < 4; j++)
#pragma unroll
            for (int r = 0; r < 4; r++) acc[i][j][r] = 0.f;

    const int nc = K >> 5;

    gfill(smg,            Ah, Al, Bh, m0, n0, 0,  K, t);
    gfill(smg + STGB,     Ah, Al, Bh, m0, n0, 32, K, t);
    gfill(smg + 2 * STGB, Ah, Al, Bh, m0, n0, 64, K, t);

    // per-lane ldmatrix byte offsets within a stage
    const int aoff = ((wm + (l & 15)) * SSTE + (l >> 4) * 8) * 2;
    const int boff = 2 * MATB + ((wn + (l & 7) + ((l >> 4) << 3)) * SSTE + ((l >> 3) & 1) * 8) * 2;

    for (int c = 0; c < nc; c++) {
        if (c <= nc - 3)      __pipeline_wait_prior(2);
        else if (c == nc - 2) __pipeline_wait_prior(1);
        else                  __pipeline_wait_prior(0);
        __syncthreads();

        unsigned sb = smem_u32(smg) + (unsigned)((c % 3) * STGB);

#pragma unroll
        for (int ks = 0; ks < 2; ks++) {
            unsigned ah[4][4], al[4][4], bh[4][2];
#pragma unroll
            for (int i = 0; i < 4; i++) {
                unsigned ao = sb + aoff + (i * 16 * SSTE + ks * 16) * 2;
                ldsm4(ah[i][0], ah[i][1], ah[i][2], ah[i][3], ao);
                ldsm4(al[i][0], al[i][1], al[i][2], al[i][3], ao + MATB);
            }
#pragma unroll
            for (int j = 0; j < 2; j++) {
                unsigned bo = sb + boff + (j * 16 * SSTE + ks * 16) * 2;
                unsigned r0, r1, r2, r3;
                ldsm4(r0, r1, r2, r3, bo);
                bh[2*j][0] = r0; bh[2*j][1] = r1; bh[2*j+1][0] = r2; bh[2*j+1][1] = r3;
            }
#pragma unroll
            for (int i = 0; i < 4; i++)
#pragma unroll
                for (int j = 0; j < 4; j++) mma16816(acc[i][j], ah[i], bh[j]);
#pragma unroll
            for (int i = 0; i < 4; i++)
#pragma unroll
                for (int j = 0; j < 4; j++) mma16816(acc[i][j], al[i], bh[j]);
        }
        __syncthreads();

        if (c + 3 < nc)
            gfill(smg + (c % 3) * STGB, Ah, Al, Bh, m0, n0, (c + 3) << 5, K, t);
    }

#pragma unroll
    for (int i = 0; i < 4; i++) {
        int m = m0 + wm + i * 16 + (l >> 2);
#pragma unroll
        for (int j = 0; j < 4; j++) {
            int n = n0 + wn + j * 8 + (l & 3) * 2;
            *(float2*)&C[(size_t)m * N + n]       = make_float2(acc[i][j][0], acc[i][j][1]);
            *(float2*)&C[(size_t)(m + 8) * N + n] = make_float2(acc[i][j][2], acc[i][j][3]);
        }
    }
}

// ---------------- fused RMSNorm + RoPE + scatter -----------------------------
__global__ __launch_bounds__(128) void normrope(
    const float* __restrict__ qkv, const int* __restrict__ positions,
    const float* __restrict__ qw, const float* __restrict__ kw)
{
    const int hh = blockIdx.x;
    const int m  = blockIdx.y;
    const int d  = threadIdx.x;
    const int b  = m >> 10, s = m & 1023;

    if (hh >= NH + NKV) {
        int vh = hh - (NH + NKV);
        g_v[((size_t)(b * NKV + vh) * S_ + s) * HD + d] =
            qkv[(size_t)m * QKV_N + V_OFF + vh * HD + d];
        return;
    }
    const bool isq = (hh < NH);
    const int off = isq ? hh * HD : K_OFF + (hh - NH) * HD;
    float x = qkv[(size_t)m * QKV_N + off + d];

    float ss = x * x;
#pragma unroll
    for (int o = 16; o; o >>= 1) ss += __shfl_xor_sync(0xffffffffu, ss, o);
    __shared__ float wsum[4];
    __shared__ float sh[128];
    if ((d & 31) == 0) wsum[d >> 5] = ss;
    __syncthreads();
    float tot = wsum[0] + wsum[1] + wsum[2] + wsum[3];
    float r = rsqrtf(tot * (1.f / HD) + 1e-6f);
    float xn = x * r * (isq ? qw[d] : kw[d]);
    sh[d] = xn;
    __syncthreads();

    int pos = positions[s];
    int i = d & 63;
    float inv = exp2f(-(float)i * (13.287712379549449f / 64.f));
    float ang = (float)pos * inv;
    float sn, cs;
    sincosf(ang, &sn, &cs);
    float out = (d < 64) ? (xn * cs - sh[d + 64] * sn)
                         : (xn * cs + sh[d - 64] * sn);
    if (isq) g_q[((size_t)(b * NH + hh) * S_ + s) * HD + d] = out;
    else     g_k[((size_t)(b * NKV + (hh - NH)) * S_ + s) * HD + d] = out;
}

// ---------------- flash attention (causal, GQA) ------------------------------
// epilogue writes fp16 hi/lo directly into g_ah/g_al (A of the O-projection).
#define SS_STRIDE 65
#define ATT_SMEM_FLOATS (8192 + 8192 + 8192 + 64 * SS_STRIDE)
#define ATT_SMEM_BYTES  (ATT_SMEM_FLOATS * 4)

__global__ __launch_bounds__(256) void attn_kernel()
{
    extern __shared__ float smf[];
    float* QsT = smf;
    float* KsT = smf + 8192;
    float* Vs  = smf + 16384;
    float* Ss  = smf + 24576;

    const int t  = threadIdx.x;
    const int qt = blockIdx.x, h = blockIdx.y, b = blockIdx.z;
    const int kh = h >> 2;
    const float* qbase = g_q + ((size_t)(b * NH + h) * S_ + qt * 64) * HD;
    const float* kbase = g_k + (size_t)(b * NKV + kh) * S_ * HD;
    const float* vbase = g_v + (size_t)(b * NKV + kh) * S_ * HD;

#pragma unroll
    for (int it = 0; it < 8; it++) {
        int idx = t + it * 256;
        int dq = idx & 31, r = idx >> 5;
        float4 v4 = *(const float4*)(qbase + r * HD + dq * 4);
        int cc = r ^ ((dq & 7) << 2);
        QsT[(dq * 4 + 0) * 64 + cc] = v4.x;
        QsT[(dq * 4 + 1) * 64 + cc] = v4.y;
        QsT[(dq * 4 + 2) * 64 + cc] = v4.z;
        QsT[(dq * 4 + 3) * 64 + cc] = v4.w;
    }

    const int tx = t & 15, ty = t >> 4;
    const int rp = t & 31, wch = t >> 5;
    const int d0 = wch * 16;
    const int r0 = rp * 2;
    const int sq0 = qt * 64;

    float m0v = -3.0e38f, m1v = -3.0e38f, l0 = 0.f, l1 = 0.f;
    float o0[16], o1[16];
#pragma unroll
    for (int i = 0; i < 16; i++) { o0[i] = 0.f; o1[i] = 0.f; }

    for (int kt = 0; kt <= qt; kt++) {
        __syncthreads();
        const float* kb = kbase + (size_t)kt * 64 * HD;
        const float* vb = vbase + (size_t)kt * 64 * HD;
#pragma unroll
        for (int it = 0; it < 8; it++) {
            int idx = t + it * 256;
            int dq = idx & 31, r = idx >> 5;
            float4 k4 = *(const float4*)(kb + r * HD + dq * 4);
            int cc = r ^ ((dq & 7) << 2);
            KsT[(dq * 4 + 0) * 64 + cc] = k4.x;
            KsT[(dq * 4 + 1) * 64 + cc] = k4.y;
            KsT[(dq * 4 + 2) * 64 + cc] = k4.z;
            KsT[(dq * 4 + 3) * 64 + cc] = k4.w;
            float4 v4 = *(const float4*)(vb + r * HD + dq * 4);
            *(float4*)&Vs[r * HD + dq * 4] = v4;
        }
        __syncthreads();

        float sc[4][4];
#pragma unroll
        for (int i = 0; i < 4; i++)
#pragma unroll
            for (int j = 0; j < 4; j++) sc[i][j] = 0.f;

        for (int dq = 0; dq < 32; dq++) {
            int sw = (dq & 7) << 2;
#pragma unroll
            for (int ii = 0; ii < 4; ii++) {
                int d = dq * 4 + ii;
                float4 a = *(const float4*)&QsT[d * 64 + ((ty * 4) ^ sw)];
                float4 bq = *(const float4*)&KsT[d * 64 + ((tx * 4) ^ sw)];
                float a0 = a.x, a1 = a.y, a2 = a.z, a3 = a.w;
                float b0 = bq.x, b1 = bq.y, b2 = bq.z, b3 = bq.w;
                sc[0][0] = fmaf(a0, b0, sc[0][0]); sc[0][1] = fmaf(a0, b1, sc[0][1]);
                sc[0][2] = fmaf(a0, b2, sc[0][2]); sc[0][3] = fmaf(a0, b3, sc[0][3]);
                sc[1][0] = fmaf(a1, b0, sc[1][0]); sc[1][1] = fmaf(a1, b1, sc[1][1]);
                sc[1][2] = fmaf(a1, b2, sc[1][2]); sc[1][3] = fmaf(a1, b3, sc[1][3]);
                sc[2][0] = fmaf(a2, b0, sc[2][0]); sc[2][1] = fmaf(a2, b1, sc[2][1]);
                sc[2][2] = fmaf(a2, b2, sc[2][2]); sc[2][3] = fmaf(a2, b3, sc[2][3]);
                sc[3][0] = fmaf(a3, b0, sc[3][0]); sc[3][1] = fmaf(a3, b1, sc[3][1]);
                sc[3][2] = fmaf(a3, b2, sc[3][2]); sc[3][3] = fmaf(a3, b3, sc[3][3]);
            }
        }
        const float scl = 0.08838834764831845f;
        const bool diag = (kt == qt);
#pragma unroll
        for (int i = 0; i < 4; i++) {
            int sq = sq0 + ty * 4 + i;
#pragma unroll
            for (int j = 0; j < 4; j++) {
                int sk = kt * 64 + tx * 4 + j;
                float val = sc[i][j] * scl;
                if (diag && sk > sq) val = -3.0e38f;
                Ss[(ty * 4 + i) * SS_STRIDE + tx * 4 + j] = val;
            }
        }
        __syncthreads();

        float tm0 = -3.0e38f, tm1 = -3.0e38f;
        for (int c = 0; c < 64; c++) {
            tm0 = fmaxf(tm0, Ss[r0 * SS_STRIDE + c]);
            tm1 = fmaxf(tm1, Ss[(r0 + 1) * SS_STRIDE + c]);
        }
        float nm0 = fmaxf(m0v, tm0), nm1 = fmaxf(m1v, tm1);
        float al0 = __expf(m0v - nm0), al1 = __expf(m1v - nm1);
        l0 *= al0; l1 *= al1;
#pragma unroll
        for (int i = 0; i < 16; i++) { o0[i] *= al0; o1[i] *= al1; }

        for (int c = 0; c < 64; c++) {
            float p0 = __expf(Ss[r0 * SS_STRIDE + c] - nm0);
            float p1 = __expf(Ss[(r0 + 1) * SS_STRIDE + c] - nm1);
            l0 += p0; l1 += p1;
            const float4* vp = (const float4*)&Vs[c * HD + d0];
#pragma unroll
            for (int q4 = 0; q4 < 4; q4++) {
                float4 vv = vp[q4];
                o0[q4*4+0] += p0 * vv.x; o0[q4*4+1] += p0 * vv.y;
                o0[q4*4+2] += p0 * vv.z; o0[q4*4+3] += p0 * vv.w;
                o1[q4*4+0] += p1 * vv.x; o1[q4*4+1] += p1 * vv.y;
                o1[q4*4+2] += p1 * vv.z; o1[q4*4+3] += p1 * vv.w;
            }
        }
        m0v = nm0; m1v = nm1;
    }

    // epilogue: normalize + fp16 hi/lo split directly into O-GEMM A buffers
    float inv0 = 1.f / l0, inv1 = 1.f / l1;
    size_t mrow = (size_t)(b * S_ + sq0 + r0);
    size_t base0 = mrow * HID + h * HD + d0;
    size_t base1 = base0 + HID;
#pragma unroll
    for (int q4 = 0; q4 < 4; q4++) {
#pragma unroll
        for (int e = 0; e < 4; e += 2) {
            float va = o0[q4*4+e]   * inv0;
            float vb = o0[q4*4+e+1] * inv0;
            __half ha = __float2half_rn(va);
            __half hb = __float2half_rn(vb);
            __half la = __float2half_rn(va - __half2float(ha));
            __half lb = __float2half_rn(vb - __half2float(hb));
            *(__half2*)(g_ah + base0 + q4*4 + e) = __halves2half2(ha, hb);
            *(__half2*)(g_al + base0 + q4*4 + e) = __halves2half2(la, lb);
            float vc = o1[q4*4+e]   * inv1;
            float vd = o1[q4*4+e+1] * inv1;
            __half hc = __float2half_rn(vc);
            __half hd = __float2half_rn(vd);
            __half lc = __float2half_rn(vc - __half2float(hc));
            __half ld = __float2half_rn(vd - __half2float(hd));
            *(__half2*)(g_ah + base1 + q4*4 + e) = __halves2half2(hc, hd);
            *(__half2*)(g_al + base1 + q4*4 + e) = __halves2half2(lc, ld);
        }
    }
}

// ---------------- launcher ---------------------------------------------------
extern "C" void kernel_launch(void* const* d_in, const int* in_sizes, int n_in,
                              void* d_out, int out_size)
{
    const float* h_shard   = (const float*)d_in[0];
    const int*   positions = (const int*)d_in[1];
    const float* w_qkv     = (const float*)d_in[2];
    const float* w_o       = (const float*)d_in[3];
    const float* qw        = (const float*)d_in[4];
    const float* kw        = (const float*)d_in[5];
    float* out = (float*)d_out;

    float* qkv_p = 0;
    __half* ah = 0;
    __half* al = 0;
    __half* bh = 0;
    cudaGetSymbolAddress((void**)&qkv_p, g_qkv);
    cudaGetSymbolAddress((void**)&ah, g_ah);
    cudaGetSymbolAddress((void**)&al, g_al);
    cudaGetSymbolAddress((void**)&bh, g_bh);

    cudaFuncSetAttribute(gemm_mma,
                         cudaFuncAttributeMaxDynamicSharedMemorySize, GSMEM);
    cudaFuncSetAttribute(attn_kernel,
                         cudaFuncAttributeMaxDynamicSharedMemorySize, ATT_SMEM_BYTES);

    const int nA  = M_TOT * HID;
    const int nBq = QKV_N * HID;
    const int nBo = HID * HID;

    split_fp16<<<nA  / 1024, 256>>>(h_shard, ah, al, nA);
    cvt_fp16<<<nBq / 1024, 256>>>(w_qkv, bh, nBq);

    gemm_mma<<<dim3(QKV_N / 128, M_TOT / 128), 256, GSMEM>>>(
        ah, al, bh, qkv_p, M_TOT, QKV_N, HID);

    normrope<<<dim3(NH + 2 * NKV, M_TOT), 128>>>(qkv_p, positions, qw, kw);

    cvt_fp16<<<nBo / 1024, 256>>>(w_o, bh, nBo);

    attn_kernel<<<dim3(S_ / 64, NH, B_), 256, ATT_SMEM_BYTES>>>();

    gemm_mma<<<dim3(HID / 128, M_TOT / 128), 256, GSMEM>>>(
        ah, al, bh, out, M_TOT, HID, HID);
}